// round 1
// baseline (speedup 1.0000x reference)
#include <cuda_runtime.h>
#include <cuda_bf16.h>
#include <math.h>

// Problem constants
#define B_SZ   16
#define C_IN   64
#define HH     256
#define WW     256
#define CKK    576          // 64*3*3
#define FC_DIM 512
#define IMG_PIX (HH * WW)   // 65536
#define N_IMG  (B_SZ * C_IN) // 1024
#define FOUT_ELEMS ((size_t)N_IMG * IMG_PIX) // 67,108,864

// Scratch for generated kernel weights [B, 576]
__device__ float g_kw[B_SZ * CKK];

// ---------------------------------------------------------------------------
// MLP kernel: one block per batch sample, 576 threads (one per output unit).
//   h = relu(F_c @ W1 + b1)        (512 -> 576)
//   logits = h @ W2 + b2           (576 -> 576)
//   kw = softmax(logits)
// Writes to g_kw scratch AND to the kernel_weights tail of d_out.
// ---------------------------------------------------------------------------
__global__ __launch_bounds__(CKK) void EKG_mlp_kernel(
    const float* __restrict__ Fc,
    const float* __restrict__ W1, const float* __restrict__ b1,
    const float* __restrict__ W2, const float* __restrict__ b2,
    float* __restrict__ kw_tail, int write_tail)
{
    __shared__ float sh_in[FC_DIM];
    __shared__ float sh_h[CKK];
    __shared__ float red[32];
    __shared__ float bcast;

    const int b = blockIdx.x;
    const int j = threadIdx.x;         // 0..575
    const int lane = j & 31;
    const int wid  = j >> 5;           // 0..17 (18 warps)

    if (j < FC_DIM) sh_in[j] = Fc[b * FC_DIM + j];
    __syncthreads();

    // Layer 1: coalesced column reads of W1 [512,576]
    float acc = b1[j];
    #pragma unroll 8
    for (int i = 0; i < FC_DIM; ++i)
        acc = fmaf(sh_in[i], W1[i * CKK + j], acc);
    sh_h[j] = fmaxf(acc, 0.0f);
    __syncthreads();

    // Layer 2
    float logit = b2[j];
    #pragma unroll 8
    for (int i = 0; i < CKK; ++i)
        logit = fmaf(sh_h[i], W2[i * CKK + j], logit);

    // ---- block softmax over 576 values ----
    // max reduce
    float m = logit;
    #pragma unroll
    for (int o = 16; o > 0; o >>= 1)
        m = fmaxf(m, __shfl_xor_sync(0xffffffffu, m, o));
    if (lane == 0) red[wid] = m;
    __syncthreads();
    if (wid == 0) {
        float v = (lane < 18) ? red[lane] : -INFINITY;
        #pragma unroll
        for (int o = 16; o > 0; o >>= 1)
            v = fmaxf(v, __shfl_xor_sync(0xffffffffu, v, o));
        if (lane == 0) bcast = v;
    }
    __syncthreads();
    const float maxv = bcast;

    float e = expf(logit - maxv);

    // sum reduce
    float s = e;
    #pragma unroll
    for (int o = 16; o > 0; o >>= 1)
        s += __shfl_xor_sync(0xffffffffu, s, o);
    __syncthreads();  // protect red[] reuse
    if (lane == 0) red[wid] = s;
    __syncthreads();
    if (wid == 0) {
        float v = (lane < 18) ? red[lane] : 0.0f;
        #pragma unroll
        for (int o = 16; o > 0; o >>= 1)
            v += __shfl_xor_sync(0xffffffffu, v, o);
        if (lane == 0) bcast = v;
    }
    __syncthreads();

    const float kw = e / bcast;
    g_kw[b * CKK + j] = kw;
    if (write_tail) kw_tail[b * CKK + j] = kw;
}

// ---------------------------------------------------------------------------
// Depthwise 3x3 conv with reflect padding.
// Block: 256 threads, processes TILE_H=8 rows x 256 cols of one (b,c) image.
// Grid: (H/TILE_H = 32, B*C = 1024).
// ---------------------------------------------------------------------------
#define TILE_H 8

__global__ __launch_bounds__(256) void EKG_conv_kernel(
    const float* __restrict__ Fd,
    float* __restrict__ out)
{
    __shared__ float sm[(TILE_H + 2)][WW + 2];   // 10 x 258 floats ~ 10.3 KB
    __shared__ float wsh[9];

    const int bc   = blockIdx.y;                 // 0..1023 (b*64+c)
    const int row0 = blockIdx.x * TILE_H;
    const int tid  = threadIdx.x;                // 0..255

    const float* __restrict__ img = Fd  + (size_t)bc * IMG_PIX;
    float*       __restrict__ o   = out + (size_t)bc * IMG_PIX;

    if (tid < 9) wsh[tid] = g_kw[bc * 9 + tid];

    // Cooperative halo load: (TILE_H+2) x 258 elements, reflect at borders.
    #pragma unroll
    for (int idx = tid; idx < (TILE_H + 2) * (WW + 2); idx += 256) {
        const int rr = idx / (WW + 2);
        const int cc = idx % (WW + 2);
        int gr = row0 + rr - 1;
        gr = (gr < 0) ? 1 : ((gr > HH - 1) ? (2 * HH - 2 - gr) : gr); // reflect
        int gc = cc - 1;
        gc = (gc < 0) ? 1 : ((gc > WW - 1) ? (WW - 2) : gc);          // reflect
        sm[rr][cc] = __ldg(img + gr * WW + gc);
    }
    __syncthreads();

    const float w00 = wsh[0], w01 = wsh[1], w02 = wsh[2];
    const float w10 = wsh[3], w11 = wsh[4], w12 = wsh[5];
    const float w20 = wsh[6], w21 = wsh[7], w22 = wsh[8];

    #pragma unroll
    for (int r = 0; r < TILE_H; ++r) {
        float v;
        v  = w00 * sm[r + 0][tid + 0];
        v  = fmaf(w01, sm[r + 0][tid + 1], v);
        v  = fmaf(w02, sm[r + 0][tid + 2], v);
        v  = fmaf(w10, sm[r + 1][tid + 0], v);
        v  = fmaf(w11, sm[r + 1][tid + 1], v);
        v  = fmaf(w12, sm[r + 1][tid + 2], v);
        v  = fmaf(w20, sm[r + 2][tid + 0], v);
        v  = fmaf(w21, sm[r + 2][tid + 1], v);
        v  = fmaf(w22, sm[r + 2][tid + 2], v);
        o[(row0 + r) * WW + tid] = v;
    }
}

// ---------------------------------------------------------------------------
// Launch
// Inputs (metadata order): F_d, F_c, W1, b1, W2, b2  (all float32)
// Output: F_out [16,64,256,256] followed by kernel_weights [16,64,3,3]
// ---------------------------------------------------------------------------
extern "C" void kernel_launch(void* const* d_in, const int* in_sizes, int n_in,
                              void* d_out, int out_size) {
    const float* Fd = (const float*)d_in[0];
    const float* Fc = (const float*)d_in[1];
    const float* W1 = (const float*)d_in[2];
    const float* b1 = (const float*)d_in[3];
    const float* W2 = (const float*)d_in[4];
    const float* b2 = (const float*)d_in[5];
    float* out = (float*)d_out;

    const int write_tail = ((size_t)out_size >= FOUT_ELEMS + (size_t)B_SZ * CKK) ? 1 : 0;
    float* kw_tail = out + FOUT_ELEMS;

    EKG_mlp_kernel<<<B_SZ, CKK>>>(Fc, W1, b1, W2, b2, kw_tail, write_tail);

    dim3 grid(HH / TILE_H, N_IMG);
    EKG_conv_kernel<<<grid, 256>>>(Fd, out);
}

// round 2
// speedup vs baseline: 1.4887x; 1.4887x over previous
#include <cuda_runtime.h>
#include <cuda_bf16.h>
#include <math.h>

#define B_SZ   16
#define C_IN   64
#define HH     256
#define WW     256
#define CKK    576
#define FC_DIM 512
#define IMG_PIX (HH * WW)
#define N_IMG  (B_SZ * C_IN)
#define FOUT_ELEMS ((size_t)N_IMG * IMG_PIX)

// Scratch
__device__ float g_h[B_SZ * CKK];       // hidden layer (post-ReLU)
__device__ float g_logits[B_SZ * CKK];  // pre-softmax
__device__ float g_kw[B_SZ * CKK];      // softmaxed kernel weights

// ---------------------------------------------------------------------------
// MLP layer 1: h = relu(F_c @ W1 + b1).  grid (3,16), block 192.
// ---------------------------------------------------------------------------
__global__ __launch_bounds__(192) void EKG_mlp1(
    const float* __restrict__ Fc,
    const float* __restrict__ W1, const float* __restrict__ b1)
{
    __shared__ float sin_[FC_DIM];
    const int b = blockIdx.y;
    const int j = blockIdx.x * 192 + threadIdx.x;
    for (int i = threadIdx.x; i < FC_DIM; i += 192) sin_[i] = Fc[b * FC_DIM + i];
    __syncthreads();
    float acc = b1[j];
    #pragma unroll 16
    for (int i = 0; i < FC_DIM; ++i)
        acc = fmaf(sin_[i], W1[i * CKK + j], acc);
    g_h[b * CKK + j] = fmaxf(acc, 0.0f);
}

// ---------------------------------------------------------------------------
// MLP layer 2: logits = h @ W2 + b2.  grid (3,16), block 192.
// ---------------------------------------------------------------------------
__global__ __launch_bounds__(192) void EKG_mlp2(
    const float* __restrict__ W2, const float* __restrict__ b2)
{
    __shared__ float sh[CKK];
    const int b = blockIdx.y;
    const int j = blockIdx.x * 192 + threadIdx.x;
    for (int i = threadIdx.x; i < CKK; i += 192) sh[i] = g_h[b * CKK + i];
    __syncthreads();
    float acc = b2[j];
    #pragma unroll 16
    for (int i = 0; i < CKK; ++i)
        acc = fmaf(sh[i], W2[i * CKK + j], acc);
    g_logits[b * CKK + j] = acc;
}

// ---------------------------------------------------------------------------
// Softmax over 576, per batch.  grid 16, block 576 (18 warps).
// ---------------------------------------------------------------------------
__global__ __launch_bounds__(CKK) void EKG_softmax(
    float* __restrict__ kw_tail, int write_tail)
{
    __shared__ float red[32];
    __shared__ float bcast;
    const int b = blockIdx.x;
    const int j = threadIdx.x;
    const int lane = j & 31;
    const int wid  = j >> 5;

    const float logit = g_logits[b * CKK + j];

    float m = logit;
    #pragma unroll
    for (int o = 16; o > 0; o >>= 1)
        m = fmaxf(m, __shfl_xor_sync(0xffffffffu, m, o));
    if (lane == 0) red[wid] = m;
    __syncthreads();
    if (wid == 0) {
        float v = (lane < 18) ? red[lane] : -INFINITY;
        #pragma unroll
        for (int o = 16; o > 0; o >>= 1)
            v = fmaxf(v, __shfl_xor_sync(0xffffffffu, v, o));
        if (lane == 0) bcast = v;
    }
    __syncthreads();
    const float e = expf(logit - bcast);

    float s = e;
    #pragma unroll
    for (int o = 16; o > 0; o >>= 1)
        s += __shfl_xor_sync(0xffffffffu, s, o);
    __syncthreads();
    if (lane == 0) red[wid] = s;
    __syncthreads();
    if (wid == 0) {
        float v = (lane < 18) ? red[lane] : 0.0f;
        #pragma unroll
        for (int o = 16; o > 0; o >>= 1)
            v += __shfl_xor_sync(0xffffffffu, v, o);
        if (lane == 0) bcast = v;
    }
    __syncthreads();

    const float kw = e / bcast;
    g_kw[b * CKK + j] = kw;
    if (write_tail) kw_tail[b * CKK + j] = kw;
}

// ---------------------------------------------------------------------------
// Depthwise 3x3 conv, reflect pad. Vectorized float4, register rotation.
// Block 256 thr: 64 col-groups (x) * 4 row-groups (y). Tile 256 x 16 rows.
// Grid (16, 1024).
// ---------------------------------------------------------------------------
#define TILE_H 16
#define SROWS  (TILE_H + 2)    // 18
#define PITCH  264             // words per smem row (mult of 4)

__global__ __launch_bounds__(256) void EKG_conv_kernel(
    const float* __restrict__ Fd,
    float* __restrict__ out)
{
    __shared__ __align__(16) float sm[SROWS * PITCH];  // 19008 B
    __shared__ float wsh[9];

    const int bc   = blockIdx.y;
    const int row0 = blockIdx.x * TILE_H;
    const int tid  = threadIdx.x;
    const int tx   = tid & 63;     // col group: cols 4tx..4tx+3
    const int ty   = tid >> 6;     // row group: output rows ty*4..ty*4+3

    const float* __restrict__ img = Fd  + (size_t)bc * IMG_PIX;
    float*       __restrict__ o   = out + (size_t)bc * IMG_PIX;

    if (tid < 9) wsh[tid] = g_kw[bc * 9 + tid];

    // ---- halo load: 18 rows, interior as float4, edges scalar ----
    const float4* __restrict__ img4 = (const float4*)img;
    #pragma unroll
    for (int i = tid; i < SROWS * 64; i += 256) {
        const int rr = i >> 6;
        const int qc = i & 63;
        int gr = row0 + rr - 1;
        gr = (gr < 0) ? 1 : ((gr > HH - 1) ? (2 * HH - 2 - gr) : gr);
        float4 v = __ldg(img4 + gr * (WW / 4) + qc);
        *(float4*)(sm + rr * PITCH + 4 + 4 * qc) = v;
    }
    if (tid < SROWS * 2) {
        const int rr   = tid >> 1;
        const int side = tid & 1;
        int gr = row0 + rr - 1;
        gr = (gr < 0) ? 1 : ((gr > HH - 1) ? (2 * HH - 2 - gr) : gr);
        if (side) sm[rr * PITCH + 4 + 256] = __ldg(img + gr * WW + (WW - 2));
        else      sm[rr * PITCH + 3]       = __ldg(img + gr * WW + 1);
    }
    __syncthreads();

    const float w00 = wsh[0], w01 = wsh[1], w02 = wsh[2];
    const float w10 = wsh[3], w11 = wsh[4], w12 = wsh[5];
    const float w20 = wsh[6], w21 = wsh[7], w22 = wsh[8];

    // 3-row register window, 6 floats per row
    float win[3][6];
    const int rbase = ty * 4;          // first output row in tile for this thread
    const int coff  = 3 + 4 * tx;      // word offset of window start within a row

    #pragma unroll
    for (int k = 0; k < 2; ++k) {
        const float* p = sm + (rbase + k) * PITCH + coff;
        win[k][0] = p[0];
        float4 q = *(const float4*)(p + 1);
        win[k][1] = q.x; win[k][2] = q.y; win[k][3] = q.z; win[k][4] = q.w;
        win[k][5] = p[5];
    }

    #pragma unroll
    for (int rr = 0; rr < 4; ++rr) {
        // load bottom row of window
        {
            const float* p = sm + (rbase + rr + 2) * PITCH + coff;
            float* w = win[(rr + 2) % 3];
            w[0] = p[0];
            float4 q = *(const float4*)(p + 1);
            w[1] = q.x; w[2] = q.y; w[3] = q.z; w[4] = q.w;
            w[5] = p[5];
        }
        const float* T = win[rr % 3];
        const float* M = win[(rr + 1) % 3];
        const float* Bt = win[(rr + 2) % 3];

        float4 r;
        r.x = w00*T[0]; r.x = fmaf(w01,T[1],r.x); r.x = fmaf(w02,T[2],r.x);
        r.x = fmaf(w10,M[0],r.x); r.x = fmaf(w11,M[1],r.x); r.x = fmaf(w12,M[2],r.x);
        r.x = fmaf(w20,Bt[0],r.x); r.x = fmaf(w21,Bt[1],r.x); r.x = fmaf(w22,Bt[2],r.x);

        r.y = w00*T[1]; r.y = fmaf(w01,T[2],r.y); r.y = fmaf(w02,T[3],r.y);
        r.y = fmaf(w10,M[1],r.y); r.y = fmaf(w11,M[2],r.y); r.y = fmaf(w12,M[3],r.y);
        r.y = fmaf(w20,Bt[1],r.y); r.y = fmaf(w21,Bt[2],r.y); r.y = fmaf(w22,Bt[3],r.y);

        r.z = w00*T[2]; r.z = fmaf(w01,T[3],r.z); r.z = fmaf(w02,T[4],r.z);
        r.z = fmaf(w10,M[2],r.z); r.z = fmaf(w11,M[3],r.z); r.z = fmaf(w12,M[4],r.z);
        r.z = fmaf(w20,Bt[2],r.z); r.z = fmaf(w21,Bt[3],r.z); r.z = fmaf(w22,Bt[4],r.z);

        r.w = w00*T[3]; r.w = fmaf(w01,T[4],r.w); r.w = fmaf(w02,T[5],r.w);
        r.w = fmaf(w10,M[3],r.w); r.w = fmaf(w11,M[4],r.w); r.w = fmaf(w12,M[5],r.w);
        r.w = fmaf(w20,Bt[3],r.w); r.w = fmaf(w21,Bt[4],r.w); r.w = fmaf(w22,Bt[5],r.w);

        *(float4*)(o + (size_t)(row0 + rbase + rr) * WW + 4 * tx) = r;
    }
}

// ---------------------------------------------------------------------------
extern "C" void kernel_launch(void* const* d_in, const int* in_sizes, int n_in,
                              void* d_out, int out_size) {
    const float* Fd = (const float*)d_in[0];
    const float* Fc = (const float*)d_in[1];
    const float* W1 = (const float*)d_in[2];
    const float* b1 = (const float*)d_in[3];
    const float* W2 = (const float*)d_in[4];
    const float* b2 = (const float*)d_in[5];
    float* out = (float*)d_out;

    const int write_tail = ((size_t)out_size >= FOUT_ELEMS + (size_t)B_SZ * CKK) ? 1 : 0;
    float* kw_tail = out + FOUT_ELEMS;

    EKG_mlp1<<<dim3(3, B_SZ), 192>>>(Fc, W1, b1);
    EKG_mlp2<<<dim3(3, B_SZ), 192>>>(W2, b2);
    EKG_softmax<<<B_SZ, CKK>>>(kw_tail, write_tail);

    dim3 grid(HH / TILE_H, N_IMG);
    EKG_conv_kernel<<<grid, 256>>>(Fd, out);
}